// round 17
// baseline (speedup 1.0000x reference)
#include <cuda_runtime.h>
#include <cuda_fp16.h>
#include <cuda_fp8.h>
#include <math.h>
#include <stdint.h>

typedef unsigned short u16;

// ---------------- problem constants ----------------
#define BATCH 32
#define IH 120
#define IW 640
#define OH1 90            // only rows 0..89 consumed by conv2
#define NCAP 3456
#define NCLS 5
#define FD 16
#define JD 80
#define NREL 25
#define K1 4800
#define K2 25600
#define NPOS 108
#define KSPLIT 8
#define NS2 1600          // conv2 k16-slices
#define NS1 150           // conv1 k32-slices (30 kh x 5)

// scaling to keep e4m3 out of subnormals: w*64, x*16 -> acc/1024
#define WSCALE 64.0f
#define XSCALE 16.0f
#define OSCALE (1.0f / 1024.0f)

// ---------------- device scratch ----------------
// conv1 B operand fp8 frags: [(b*120+row)*5+sp][nf 0..15][lane][2 u32]
__device__ uint32_t g_inf8[(size_t)BATCH * IH * 5 * 16 * 32 * 2];
// conv1 A operand fp8 frags: [s32*16+rb][lane][4 u32]
__device__ uint4 g_w1f8[NS1 * 16 * 32];
// conv2 A operand fp16 frags: [s2*16+rb][lane][4 u32]
__device__ uint4 g_w2f[NS2 * 16 * 32];
// conv2 B operand (conv1 out, fp16): [b][s2][nf][lane][2 u32]
__device__ uint32_t g_bf2[(size_t)BATCH * NS2 * 16 * 64];
__device__ float g_prim4[KSPLIT][BATCH * 256 * NPOS];
__device__ __half g_up[(size_t)BATCH * NCAP * JD];

// ---------------- helpers ----------------
__device__ __forceinline__ void mma16816(float* c, const uint32_t* a,
                                         const uint32_t* b) {
    asm volatile(
        "mma.sync.aligned.m16n8k16.row.col.f32.f16.f16.f32 "
        "{%0,%1,%2,%3}, {%4,%5,%6,%7}, {%8,%9}, {%0,%1,%2,%3};"
        : "+f"(c[0]), "+f"(c[1]), "+f"(c[2]), "+f"(c[3])
        : "r"(a[0]), "r"(a[1]), "r"(a[2]), "r"(a[3]), "r"(b[0]), "r"(b[1]));
}
__device__ __forceinline__ void mma16832f8(float* c, const uint32_t* a,
                                           const uint32_t* b) {
    asm volatile(
        "mma.sync.aligned.m16n8k32.row.col.f32.e4m3.e4m3.f32 "
        "{%0,%1,%2,%3}, {%4,%5,%6,%7}, {%8,%9}, {%0,%1,%2,%3};"
        : "+f"(c[0]), "+f"(c[1]), "+f"(c[2]), "+f"(c[3])
        : "r"(a[0]), "r"(a[1]), "r"(a[2]), "r"(a[3]), "r"(b[0]), "r"(b[1]));
}
__device__ __forceinline__ void cp16(uint32_t dst, const void* src) {
    asm volatile("cp.async.ca.shared.global [%0], [%1], 16;"
                 :: "r"(dst), "l"(src));
}
__device__ __forceinline__ void cp_commit() {
    asm volatile("cp.async.commit_group;");
}
__device__ __forceinline__ void cp_wait0() {
    asm volatile("cp.async.wait_group 0;");
}
__device__ __forceinline__ uint32_t pack2h(float v0, float v1) {
    __half2 h = __floats2half2_rn(v0, v1);
    return *(uint32_t*)&h;
}
__device__ __forceinline__ unsigned char to8(float v) {
    return (unsigned char)__nv_cvt_float_to_fp8(v, __NV_SATFINITE, __NV_E4M3);
}
__device__ __forceinline__ void unpack8(uint4 v, float* f) {
    const __half2* h = (const __half2*)&v;
#pragma unroll
    for (int q = 0; q < 4; ++q) {
        float2 t = __half22float2(h[q]);
        f[2 * q] = t.x;
        f[2 * q + 1] = t.y;
    }
}

// =====================================================================
// prep: input -> conv1 fp8 B fragment order (x16 scaled).
// u32 idx: w(reg), lane, nf, sp, rowb.
// col = 4*(nf*8+grp) + sp*32 + 4*tig + 16*w + byte
// =====================================================================
__global__ void prep_inf8(const float* __restrict__ in,
                          uint32_t* __restrict__ inf8) {
    size_t idx = (size_t)blockIdx.x * 256 + threadIdx.x;
    if (idx >= (size_t)BATCH * IH * 5 * 16 * 32 * 2) return;
    int w = idx & 1;
    int lane = (idx >> 1) & 31;
    int nf = (idx >> 6) & 15;
    size_t t = idx >> 10;
    int sp = (int)(t % 5);
    size_t rowb = t / 5;
    int grp = lane >> 2, tig = lane & 3;
    int col0 = 4 * (nf * 8 + grp) + sp * 32 + 4 * tig + 16 * w;
    uint32_t r = 0;
#pragma unroll
    for (int by = 0; by < 4; ++by) {
        int col = col0 + by;
        float v = (col < IW) ? in[rowb * IW + col] * XSCALE : 0.0f;
        r |= (uint32_t)to8(v) << (8 * by);
    }
    inf8[idx] = r;
}

// =====================================================================
// prep conv1 weights -> fp8 A fragment order (x64 scaled).
// j: bit0 -> row+8, bit1 -> k+16.  kk = 4*tig + 16*(j>>1) + byte
// =====================================================================
__global__ void prep_c1wf8(const float* __restrict__ w,
                           uint32_t* __restrict__ w1f8) {
    int idx = blockIdx.x * 256 + threadIdx.x;   // 307200 u32
    if (idx >= NS1 * 16 * 32 * 4) return;
    int j = idx & 3;
    int lane = (idx >> 2) & 31;
    int rb = (idx >> 7) & 15;
    int s32 = idx >> 11;
    int grp = lane >> 2, tig = lane & 3;
    int c = rb * 16 + grp + (j & 1) * 8;
    int kh = s32 / 5, sp = s32 - 5 * kh;
    int kbase = kh * 160 + sp * 32 + 4 * tig + 16 * (j >> 1);
    uint32_t r = 0;
#pragma unroll
    for (int by = 0; by < 4; ++by)
        r |= (uint32_t)to8(w[(size_t)c * K1 + kbase + by] * WSCALE) << (8 * by);
    w1f8[idx] = r;
}

// =====================================================================
// prep conv2 weights -> fp16 A fragment order (unchanged).
// =====================================================================
__global__ void prep_c2wf(const float* __restrict__ w2,
                          uint32_t* __restrict__ w2f) {
    int idx = blockIdx.x * 256 + threadIdx.x;   // 3,276,800
    if (idx >= NS2 * 16 * 32 * 4) return;
    int j = idx & 3;
    int lane = (idx >> 2) & 31;
    int rb = (idx >> 7) & 15;
    int s2 = idx >> 11;
    int grp = lane >> 2, tig = lane & 3;
    int c2 = rb * 16 + grp + (j & 1) * 8;
    int k0 = s2 * 16 + 2 * tig + (j >> 1) * 8;
    float v0 = w2[((size_t)c2 * 256 + (k0 & 255)) * 100 + (k0 >> 8)];
    float v1 = w2[((size_t)c2 * 256 + ((k0 + 1) & 255)) * 100 + ((k0 + 1) >> 8)];
    w2f[idx] = pack2h(v0, v1);
}

// =====================================================================
// conv1 via fp8 HMMA (m16n8k32). CTA = (mt, oh, b): M128 x N128 x K4800.
// 8 warps 2(M)x4(N), warp 64x32, 2 CTAs/SM. A: kh-row (5 k32-slices,
// 20KB) cp.async double buffer. B: LDG.64 frags. Epilogue /1024 + bias
// + relu -> fp16 conv2-B-fragment order (unchanged downstream).
// =====================================================================
__global__ __launch_bounds__(256, 2)
void conv1_mma(const uint32_t* __restrict__ inf8,
               const uint4* __restrict__ w1f8,
               const float* __restrict__ bias, u16* __restrict__ bf2) {
    extern __shared__ uint4 sA[];   // [2][1280]: sp*256 + rb*32 + lane

    const int tid = threadIdx.x;
    const int wid = tid >> 5, lane = tid & 31;
    const int grp = lane >> 2, tig = lane & 3;
    const int wm = wid >> 2, wn = wid & 3;
    const int mt = blockIdx.x, oh = blockIdx.y, b = blockIdx.z;

    float acc[4][4][4] = {};

    const uint32_t sA0 = (uint32_t)__cvta_generic_to_shared(&sA[0]);

    auto stageA = [&](int it, int stg) {
#pragma unroll
        for (int r = 0; r < 5; ++r) {
            const int c = tid + (r << 8);              // 0..1279
            const int sp = c >> 8;
            const int rbl = (c >> 5) & 7;
            const int ln = c & 31;
            const int s32 = it * 5 + sp;
            cp16(sA0 + (stg * 1280 + c) * 16,
                 w1f8 + ((s32 * 16 + mt * 8 + rbl) * 32 + ln));
        }
        cp_commit();
    };

    stageA(0, 0);
    cp_wait0();
    __syncthreads();

    const uint2* inf2 = (const uint2*)inf8;

    for (int it = 0; it < 30; ++it) {                  // it = kh
        const int stg = it & 1;
        if (it < 29) stageA(it + 1, stg ^ 1);

        const size_t rowb = (size_t)b * IH + oh + it;
        const uint2* bb = inf2 + ((rowb * 5) * 16 + wn * 4) * 32 + lane;
#pragma unroll
        for (int sp = 0; sp < 5; ++sp) {
            uint2 bf[4];
#pragma unroll
            for (int nf = 0; nf < 4; ++nf)
                bf[nf] = bb[(sp * 16 + nf) * 32];
            uint4 af[4];
#pragma unroll
            for (int mf = 0; mf < 4; ++mf)
                af[mf] = sA[stg * 1280 + sp * 256 + (wm * 4 + mf) * 32 + lane];
#pragma unroll
            for (int mf = 0; mf < 4; ++mf)
#pragma unroll
                for (int nf = 0; nf < 4; ++nf)
                    mma16832f8(acc[mf][nf], (const uint32_t*)&af[mf],
                               (const uint32_t*)&bf[nf]);
        }
        cp_wait0();
        __syncthreads();
    }

    // epilogue: unscale + bias + relu -> fp16, conv2-B-fragment order.
    const int ohh = oh / 10, kh2 = oh - 10 * ohh;
#pragma unroll
    for (int mf = 0; mf < 4; ++mf) {
#pragma unroll
        for (int nf = 0; nf < 4; ++nf) {
#pragma unroll
            for (int i = 0; i < 4; ++i) {
                const int c = mt * 128 + wm * 64 + mf * 16 + grp + (i >> 1) * 8;
                const int ow = wn * 32 + nf * 8 + 2 * tig + (i & 1);
                if (ow < 120) {
                    float v = fmaxf(acc[mf][nf][i] * OSCALE + bias[c], 0.0f);
                    const int pos = ohh * 12 + ow / 10;
                    const int r = kh2 * 10 + (ow % 10);
                    const int s2 = r * 16 + mt * 8 + wm * 4 + mf;
                    const int lane2 = (pos & 7) * 4 + (grp >> 1);
                    const size_t o =
                        ((((size_t)b * NS2 + s2) * 16 + (pos >> 3)) * 32 +
                         lane2) * 4 + (i >> 1) * 2 + (grp & 1);
                    bf2[o] = __half_as_ushort(__float2half_rn(v));
                }
            }
        }
    }
}

// =====================================================================
// conv2 via fp16 HMMA, barrier-free fragment-order (unchanged).
// =====================================================================
__global__ __launch_bounds__(256, 2)
void conv2_mma(const uint32_t* __restrict__ bf2, const uint4* __restrict__ w2f,
               const float* __restrict__ pb, float* __restrict__ prim4) {
    const int tid = threadIdx.x;
    const int wid = tid >> 5, lane = tid & 31;
    const int grp = lane >> 2, tig = lane & 3;
    const int wm = wid >> 2, wn = wid & 3;
    const int mt = blockIdx.x, b = blockIdx.y, ks = blockIdx.z;

    float acc[4][4][4] = {};

    const int NSL = NS2 / KSPLIT;   // 200
    const uint4* Ab = w2f + ((size_t)(ks * NSL) * 16 + mt * 8 + wm * 4) * 32 +
                      lane;
    const uint32_t* Bb = bf2 + (((size_t)b * NS2 + ks * NSL) * 16 + wn * 4) *
                         64 + lane * 2;

    for (int s = 0; s < NSL; ++s) {
        uint2 bfr[4];
#pragma unroll
        for (int nf = 0; nf < 4; ++nf)
            bfr[nf] = *(const uint2*)(Bb + (size_t)s * 1024 + nf * 64);
        uint4 af[4];
#pragma unroll
        for (int mf = 0; mf < 4; ++mf)
            af[mf] = Ab[((size_t)s * 16 + mf) * 32];
#pragma unroll
        for (int mf = 0; mf < 4; ++mf)
#pragma unroll
            for (int nf = 0; nf < 4; ++nf)
                mma16816(acc[mf][nf], (const uint32_t*)&af[mf],
                         (const uint32_t*)&bfr[nf]);
    }

    float* outp = prim4 + (size_t)ks * (BATCH * 256 * NPOS);
#pragma unroll
    for (int mf = 0; mf < 4; ++mf) {
#pragma unroll
        for (int nf = 0; nf < 4; ++nf) {
#pragma unroll
            for (int i = 0; i < 4; ++i) {
                const int c2 = mt * 128 + wm * 64 + mf * 16 + grp + (i >> 1) * 8;
                const int n = (wn * 4 + nf) * 8 + 2 * tig + (i & 1);
                if (n < NPOS) {
                    float v = acc[mf][nf][i] + (ks == 0 ? pb[c2] : 0.0f);
                    outp[((size_t)b * 256 + c2) * NPOS + n] = v;
                }
            }
        }
    }
}

// =====================================================================
// squash + caps prediction (sums KSPLIT conv2 partials), fp16 output
// =====================================================================
__global__ void squash_predict_kernel(const float* __restrict__ prim4,
                                      const float* __restrict__ caps_w,
                                      __half* __restrict__ up) {
    __shared__ float su[8];
    __shared__ float sfac;
    const int i = blockIdx.x;
    const int b = blockIdx.y;
    const int g = i / NPOS;
    const int p = i - g * NPOS;
    const int t = threadIdx.x;
    const int SL = BATCH * 256 * NPOS;

    if (t < 8) {
        size_t o = ((size_t)b * 256 + g * 8 + t) * NPOS + p;
        float acc = 0.0f;
#pragma unroll
        for (int q = 0; q < KSPLIT; ++q) acc += prim4[o + (size_t)q * SL];
        su[t] = acc;
    }
    __syncthreads();
    if (t == 0) {
        float l2 = 0.0f;
#pragma unroll
        for (int d = 0; d < 8; ++d) l2 += su[d] * su[d];
        sfac = sqrtf(l2) / (1.0f + l2);
    }
    __syncthreads();
    const float f = sfac;
    const float* cw = caps_w + (size_t)i * 8 * JD + t;
    float a = 0.0f;
#pragma unroll
    for (int d = 0; d < 8; ++d) a += su[d] * f * cw[d * JD];
    up[((size_t)b * NCAP + i) * JD + t] = __float2half_rn(a);
}

// =====================================================================
// FUSED routing (4 iterations) + heads (unchanged from R16).
// =====================================================================
#define RSM_BB 0
#define RSM_FIN (NCAP * NCLS)
#define RSM_FAC (RSM_FIN + 80)
#define RSM_PART (RSM_FAC + 8)
#define RSM_V (RSM_PART + 8 * 80)
#define RSM_TOT (RSM_V + 80)

__global__ __launch_bounds__(256, 1)
void route_all(const __half* __restrict__ up, const float* __restrict__ b_route,
               const float* __restrict__ pred_w,
               const float* __restrict__ pred_b,
               const float* __restrict__ eos_w,
               const float* __restrict__ eos_b, float* __restrict__ out) {
    extern __shared__ float rs[];
    float* s_bb = rs + RSM_BB;
    float* s_fin = rs + RSM_FIN;
    float* s_fac = rs + RSM_FAC;
    float* s_part = rs + RSM_PART;
    float* s_v = rs + RSM_V;

    const int b = blockIdx.x;
    const int t = threadIdx.x;
    const int lane = t & 31, wid = t >> 5;
    const __half* upb = up + (size_t)b * NCAP * JD;

    auto reduce_squash = [&](float sd[NCLS][FD]) {
#pragma unroll
        for (int o = 0; o < NCLS; ++o)
#pragma unroll
            for (int d = 0; d < FD; ++d)
#pragma unroll
                for (int off = 16; off; off >>= 1)
                    sd[o][d] += __shfl_down_sync(0xffffffffu, sd[o][d], off);
        if (lane == 0)
#pragma unroll
            for (int o = 0; o < NCLS; ++o)
#pragma unroll
                for (int d = 0; d < FD; ++d)
                    s_part[wid * 80 + o * FD + d] = sd[o][d];
        __syncthreads();
        if (t < 80) {
            float tot = 0.0f;
#pragma unroll
            for (int w = 0; w < 8; ++w) tot += s_part[w * 80 + t];
            s_fin[t] = tot;
        }
        __syncthreads();
        if (t < NCLS) {
            float l2 = 0.0f;
#pragma unroll
            for (int d = 0; d < FD; ++d) {
                float x = s_fin[t * FD + d];
                l2 += x * x;
            }
            s_fac[t] = sqrtf(l2) / (1.0f + l2);
        }
        __syncthreads();
        if (t < 80) s_v[t] = s_fin[t] * s_fac[t / FD];
        __syncthreads();
    };

    // ---- iteration 0 ----
    {
        float sd[NCLS][FD] = {};
        for (int i = t; i < NCAP; i += 256) {
            float br[NCLS];
#pragma unroll
            for (int o = 0; o < NCLS; ++o) br[o] = b_route[i * NCLS + o];
            float m = br[0];
#pragma unroll
            for (int o = 1; o < NCLS; ++o) m = fmaxf(m, br[o]);
            float ssum = 0.0f;
            float ce[NCLS];
#pragma unroll
            for (int o = 0; o < NCLS; ++o) {
                ce[o] = expf(br[o] - m);
                ssum += ce[o];
            }
            const float inv = 1.0f / ssum;
            const uint4* u4 = (const uint4*)(upb + (size_t)i * JD);
#pragma unroll
            for (int o = 0; o < NCLS; ++o) {
                float uo[FD];
                unpack8(u4[o * 2], uo);
                unpack8(u4[o * 2 + 1], uo + 8);
                const float ci = ce[o] * inv;
#pragma unroll
                for (int d = 0; d < FD; ++d) sd[o][d] += ci * uo[d];
            }
        }
        reduce_squash(sd);
    }

    // ---- 3 routing iterations ----
    for (int it = 0; it < 3; ++it) {
        float sd[NCLS][FD] = {};
        for (int i = t; i < NCAP; i += 256) {
            const uint4* u4 = (const uint4*)(upb + (size_t)i * JD);
            float uall[NCLS][FD];
            float nb[NCLS];
#pragma unroll
            for (int o = 0; o < NCLS; ++o) {
                unpack8(u4[o * 2], uall[o]);
                unpack8(u4[o * 2 + 1], uall[o] + 8);
                float dot = 0.0f;
#pragma unroll
                for (int d = 0; d < FD; ++d) dot += uall[o][d] * s_v[o * FD + d];
                float prev = (it == 0) ? b_route[i * NCLS + o]
                                       : s_bb[i * NCLS + o];
                nb[o] = prev + dot;
                s_bb[i * NCLS + o] = nb[o];
            }
            float m = nb[0];
#pragma unroll
            for (int o = 1; o < NCLS; ++o) m = fmaxf(m, nb[o]);
            float ssum = 0.0f;
#pragma unroll
            for (int o = 0; o < NCLS; ++o) {
                nb[o] = expf(nb[o] - m);
                ssum += nb[o];
            }
            const float inv = 1.0f / ssum;
#pragma unroll
            for (int o = 0; o < NCLS; ++o) {
                const float ci = nb[o] * inv;
#pragma unroll
                for (int d = 0; d < FD; ++d) sd[o][d] += ci * uall[o][d];
            }
        }
        __syncthreads();
        reduce_squash(sd);
    }

    // ---- heads ----
    if (t < NCLS) {
        const float* vv = s_v + t * FD;
        float lg[NREL + 1];
#pragma unroll 4
        for (int r = 0; r < NREL; ++r) {
            float a = pred_b[r];
#pragma unroll
            for (int d = 0; d < FD; ++d) a += vv[d] * pred_w[r * FD + d];
            lg[r] = a;
        }
        {
            float a = eos_b[0];
#pragma unroll
            for (int d = 0; d < FD; ++d) a += vv[d] * eos_w[d];
            lg[NREL] = a;
        }
        float m = lg[0];
#pragma unroll
        for (int k = 1; k <= NREL; ++k) m = fmaxf(m, lg[k]);
        float s = 0.0f;
#pragma unroll
        for (int k = 0; k <= NREL; ++k) s += expf(lg[k] - m);
        const float ls = m + logf(s);
#pragma unroll
        for (int k = 0; k <= NREL; ++k)
            out[((size_t)b * NCLS + t) * (NREL + 1) + k] = lg[k] - ls;
    }
}

// =====================================================================
extern "C" void kernel_launch(void* const* d_in, const int* in_sizes, int n_in,
                              void* d_out, int out_size) {
    const float* input   = (const float*)d_in[0];
    const float* conv1_w = (const float*)d_in[1];
    const float* conv1_b = (const float*)d_in[2];
    const float* prim_w  = (const float*)d_in[3];
    const float* prim_b  = (const float*)d_in[4];
    const float* caps_w  = (const float*)d_in[5];
    const float* b_route = (const float*)d_in[6];
    const float* pred_w  = (const float*)d_in[7];
    const float* pred_b  = (const float*)d_in[8];
    const float* eos_w   = (const float*)d_in[9];
    const float* eos_b   = (const float*)d_in[10];
    float* out = (float*)d_out;

    uint32_t *inf8p, *bf2p;
    uint4 *w1f8p, *w2fp;
    float* prim4;
    __half* upp;
    cudaGetSymbolAddress((void**)&inf8p, g_inf8);
    cudaGetSymbolAddress((void**)&w1f8p, g_w1f8);
    cudaGetSymbolAddress((void**)&w2fp, g_w2f);
    cudaGetSymbolAddress((void**)&bf2p, g_bf2);
    cudaGetSymbolAddress((void**)&prim4, g_prim4);
    cudaGetSymbolAddress((void**)&upp, g_up);

    const size_t NIN8 = (size_t)BATCH * IH * 5 * 16 * 32 * 2;
    const int SMEM_C1 = 2 * 1280 * 16;          // 40KB
    const int SMEM_RT = RSM_TOT * 4;            // ~72KB

    cudaFuncSetAttribute(conv1_mma, cudaFuncAttributeMaxDynamicSharedMemorySize,
                         SMEM_C1);
    cudaFuncSetAttribute(route_all, cudaFuncAttributeMaxDynamicSharedMemorySize,
                         SMEM_RT);

    prep_inf8<<<(unsigned)((NIN8 + 255) / 256), 256>>>(input, inf8p);
    prep_c1wf8<<<(NS1 * 16 * 32 * 4 + 255) / 256, 256>>>(conv1_w,
                                                         (uint32_t*)w1f8p);
    prep_c2wf<<<(NS2 * 16 * 32 * 4 + 255) / 256, 256>>>(prim_w,
                                                        (uint32_t*)w2fp);
    conv1_mma<<<dim3(2, OH1, BATCH), 256, SMEM_C1>>>(inf8p, w1f8p, conv1_b,
                                                     (u16*)bf2p);
    conv2_mma<<<dim3(2, BATCH, KSPLIT), 256>>>(bf2p, w2fp, prim_b, prim4);
    squash_predict_kernel<<<dim3(NCAP, BATCH), 80>>>(prim4, caps_w, upp);
    route_all<<<BATCH, 256, SMEM_RT>>>(upp, b_route, pred_w, pred_b,
                                       eos_w, eos_b, out);
}